// round 3
// baseline (speedup 1.0000x reference)
#include <cuda_runtime.h>

#define S      771            // STATE
#define SP     772            // padded (col 771 is a hard zero)
#define NB     32             // batch (== warp lanes)
#define NT     128            // time
#define NCTA   97             // 97*8 = 776 >= 772 columns
#define WJ     8              // output columns per CTA
#define NWARP  16
#define NTHR   512
#define NGRP   193            // ceil(772/4) i-groups of 4
#define WFLT   (NGRP*128)     // floats per timestep (packed layout)

typedef unsigned long long ull;

// ---------------- persistent device state ----------------
// W[t][ (i>>2)*128 + lane*4 + (i&3) ]  -- 4 consecutive i per lane => LDG.128
__device__ float    g_W[NT][WFLT];          // 12.65 MB, fits in L2
__device__ unsigned g_flag[NT][NCTA];       // monotone epoch flags (never reset)
__device__ float    g_dh[NT][NB];           // d history (CTA0 only)
__device__ float    g_scp[NCTA][NB];        // per-CTA score partials

static __device__ __forceinline__ unsigned ldacq(const unsigned* p) {
    unsigned v;
    asm volatile("ld.acquire.gpu.global.b32 %0,[%1];" : "=r"(v) : "l"(p) : "memory");
    return v;
}
static __device__ __forceinline__ void strel(unsigned* p, unsigned v) {
    asm volatile("st.release.gpu.global.b32 [%0],%1;" :: "l"(p), "r"(v) : "memory");
}
static __device__ __forceinline__ ull pk2(float x, float y) {
    ull r; asm("mov.b64 %0,{%1,%2};" : "=l"(r) : "f"(x), "f"(y)); return r;
}
static __device__ __forceinline__ void upk2(ull v, float& x, float& y) {
    asm("mov.b64 {%0,%1},%2;" : "=f"(x), "=f"(y) : "l"(v));
}
static __device__ __forceinline__ void ffma2(ull& a, ull b, ull c) {   // a += b*c (2x f32)
    asm("fma.rn.f32x2 %0,%1,%2,%0;" : "+l"(a) : "l"(b), "l"(c));
}
static __device__ __forceinline__ void fadd2(ull& a, ull b) {          // a += b
    asm("add.rn.f32x2 %0,%1,%0;" : "+l"(a) : "l"(b));
}

#define PIDX(j) ((((j) >> 2) << 7) + (lane << 2) + ((j) & 3))

__global__ void __launch_bounds__(NTHR, 1)
crf_kernel(const float* __restrict__ em, const int* __restrict__ tags32,
           const float* __restrict__ mask, const float* __restrict__ trans,
           float* __restrict__ out)
{
    __shared__ __align__(16) float ET[SP][WJ];      // exp(trans) col slice, [i][jc]
    __shared__ float s_part[NWARP][WJ][NB];
    __shared__ float s_d[NWARP][NB];

    const int tid  = threadIdx.x;
    const int w    = tid >> 5;
    const int lane = tid & 31;                      // lane == batch index
    const int cta  = blockIdx.x;
    const int j0   = cta * WJ;

    // epoch for this run: my own last-step flag, +1 (replay-safe, no reset kernel)
    const unsigned runv = __ldcg(&g_flag[NT-1][cta]) + 1u;

    // =============== INIT ===============
    // exp(transitions) column slice into smem (out-of-range cols -> 0)
    for (int idx = tid; idx < SP * WJ; idx += NTHR) {
        int i = idx >> 3, jc = idx & 7, j = j0 + jc;
        float v = 0.f;
        if (i < S && j < S) v = __expf(trans[i * S + j]);   // exp(-1e9) -> 0
        (&ET[0][0])[idx] = v;
    }
    // W_0 slice: W0[j][b] = exp(trans[BOS=0][j] + em[b,0,j]); col 771 -> 0
    if (w < WJ) {
        int j = j0 + w;
        if (j < SP) {
            float v = 0.f;
            if (j < S) v = __expf(trans[j] + em[(size_t)lane * NT * S + j]);
            g_W[0][PIDX(j)] = v;
        }
    }
    // score gather: CTA c covers t = c+1, c+98 (lane = batch)
    if (w == NWARP - 1) {
        const bool is64 = (tags32[1] == 0);   // int64 high words are zero (tags >= 3)
        const int b = lane;
        float sc = 0.f;
        for (int t = cta + 1; t < NT; t += NCTA) {
            float m  = mask[b * NT + t];
            int cur  = is64 ? tags32[(b * NT + t) * 2]     : tags32[b * NT + t];
            int prv  = is64 ? tags32[(b * NT + t - 1) * 2] : tags32[b * NT + t - 1];
            sc += (em[((size_t)b * NT + t) * S + cur] + trans[prv * S + cur]) * m;
        }
        if (cta == NCTA - 1) {   // boundary terms
            int tag0 = is64 ? tags32[(b * NT) * 2] : tags32[b * NT];
            sc += trans[tag0] + em[(size_t)b * NT * S + tag0];      // BOS -> tag0 + em0
            float ms = 0.f;
            for (int t = 0; t < NT; t++) ms += mask[b * NT + t];
            int li = (int)ms - 1;
            int lt = is64 ? tags32[(b * NT + li) * 2] : tags32[b * NT + li];
            sc += trans[lt * S + 1];                                 // last -> EOS
        }
        g_scp[cta][lane] = sc;
    }
    __syncthreads();
    if (tid == 0) strel(&g_flag[0][cta], runv);

    // warp work split: 4-wide i-groups; warp 15 takes the tail group
    const int g0  = 12 * w;
    const int g1  = (w == NWARP - 1) ? NGRP : g0 + 12;
    const int sl0 = 6 * w;
    const int nfl = (w == NWARP - 1) ? 7 : 6;

    // =============== MAIN LOOP: 127 dataflow matvec steps ===============
    for (int t = 1; t < NT; ++t) {
        const float* __restrict__ Wp = g_W[t - 1];
        float*       __restrict__ Wc = g_W[t];

        // prefetch input-side scalars (independent of producers)
        float mk = 0.f, emv = 0.f, oldv = 0.f;
        const int j = j0 + w;
        if (w < WJ && j < SP) {
            mk = mask[lane * NT + t];
            if (j < S) emv = em[((size_t)lane * NT + t) * S + j];
            oldv = __ldcg(&Wp[PIDX(j)]);     // own-CTA data, already visible
        }

        // wait for the producer slices this warp consumes
        if (lane < nfl) {
            const unsigned* f = &g_flag[t - 1][sl0 + lane];
            while (ldacq(f) != runv) __nanosleep(64);
        }
        __syncwarp();

        ull a0 = 0, a1 = 0, a2 = 0, a3 = 0, dp = 0;
        const float4* W4 = (const float4*)Wp;
        float4 u = __ldcg(&W4[g0 * 32 + lane]);
        for (int g = g0; g < g1; ++g) {
            float4 un = u;
            if (g + 1 < g1) un = __ldcg(&W4[(g + 1) * 32 + lane]);
            const ulonglong2* er = (const ulonglong2*)&ET[g << 2][0];
            {   ull uu = pk2(u.x, u.x); ulonglong2 ea = er[0], eb = er[1];
                ffma2(a0, uu, ea.x); ffma2(a1, uu, ea.y);
                ffma2(a2, uu, eb.x); ffma2(a3, uu, eb.y); }
            {   ull uu = pk2(u.y, u.y); ulonglong2 ea = er[2], eb = er[3];
                ffma2(a0, uu, ea.x); ffma2(a1, uu, ea.y);
                ffma2(a2, uu, eb.x); ffma2(a3, uu, eb.y); }
            {   ull uu = pk2(u.z, u.z); ulonglong2 ea = er[4], eb = er[5];
                ffma2(a0, uu, ea.x); ffma2(a1, uu, ea.y);
                ffma2(a2, uu, eb.x); ffma2(a3, uu, eb.y); }
            {   ull uu = pk2(u.w, u.w); ulonglong2 ea = er[6], eb = er[7];
                ffma2(a0, uu, ea.x); ffma2(a1, uu, ea.y);
                ffma2(a2, uu, eb.x); ffma2(a3, uu, eb.y); }
            fadd2(dp, pk2(u.x, u.y));        // local normalizer (fixed order,
            fadd2(dp, pk2(u.z, u.w));        //  bitwise identical in every CTA)
            u = un;
        }

        float cs[8];
        upk2(a0, cs[0], cs[1]); upk2(a1, cs[2], cs[3]);
        upk2(a2, cs[4], cs[5]); upk2(a3, cs[6], cs[7]);
        float dx, dy; upk2(dp, dx, dy);
        #pragma unroll
        for (int k = 0; k < WJ; k++) s_part[w][k][lane] = cs[k];
        s_d[w][lane] = dx + dy;
        __syncthreads();                      // (a)

        if (w < WJ) {
            float ssum = 0.f, dsum = 0.f;
            #pragma unroll
            for (int ww = 0; ww < NWARP; ww++) {
                ssum += s_part[ww][w][lane];
                dsum += s_d[ww][lane];
            }
            if (j < SP) {
                float nv = (mk > 0.f)
                         ? (ssum * __fdividef(1.f, dsum) * __expf(emv))
                         : oldv;              // masked step carries old value
                Wc[PIDX(j)] = nv;             // col 771 stays 0 automatically
            }
            if (cta == 0 && w == 0) g_dh[t - 1][lane] = dsum;
        }
        __syncthreads();                      // (b) — orders Wc stores before flag
        if (tid == 0) strel(&g_flag[t][cta], runv);
    }

    // =============== FINAL: log_z + score -> NLL (CTA 0) ===============
    if (cta == 0) {
        for (int s = tid; s < NCTA; s += NTHR) {
            const unsigned* f = &g_flag[NT - 1][s];
            while (ldacq(f) != runv) __nanosleep(64);
        }
        __syncthreads();

        const int b = lane;
        float Lp = 0.f;
        for (int t = 1 + w; t < NT; t += NWARP)
            if (mask[b * NT + t] > 0.f) Lp += logf(g_dh[t - 1][b]);

        float zp = 0.f;
        const float* Wf = g_W[NT - 1];
        for (int jj = w; jj < S; jj += NWARP)
            zp += __ldcg(&Wf[PIDX(jj)]) * __expf(trans[jj * S + 1]);   // trans[j, EOS]

        s_part[w][0][lane] = Lp;
        s_part[w][1][lane] = zp;
        __syncthreads();
        if (w == 0) {
            float L = 0.f, zs = 0.f;
            #pragma unroll
            for (int ww = 0; ww < NWARP; ww++) {
                L  += s_part[ww][0][lane];
                zs += s_part[ww][1][lane];
            }
            float sc = 0.f;
            for (int c = 0; c < NCTA; c++) sc += g_scp[c][lane];
            float r = (L + logf(zs)) - sc;    // log_z - score, per batch
            #pragma unroll
            for (int o = 16; o; o >>= 1) r += __shfl_xor_sync(0xffffffffu, r, o);
            if (lane == 0) out[0] = r;        // NLL
        }
    }
}

extern "C" void kernel_launch(void* const* d_in, const int* in_sizes, int n_in,
                              void* d_out, int out_size)
{
    (void)in_sizes; (void)n_in; (void)out_size;
    const float* em    = (const float*)d_in[0];
    const int*   tags  = (const int*)  d_in[1];   // int64 or int32, detected in-kernel
    const float* mask  = (const float*)d_in[2];
    const float* trans = (const float*)d_in[3];
    crf_kernel<<<NCTA, NTHR>>>(em, tags, mask, trans, (float*)d_out);
}

// round 4
// speedup vs baseline: 1.8915x; 1.8915x over previous
#include <cuda_runtime.h>

#define S      771             // STATE
#define NB     32              // batch == warp lanes
#define NT     128             // time
#define NCTA   97              // 97*8 = 776 >= 772 output columns
#define WJ     8               // output columns per CTA
#define NWARP  16
#define NTHR   512
#define GW     13              // i-groups (of 4 states) per warp, uniform
#define NGTOT  (NWARP*GW)      // 208 groups = 832 padded states
#define WFLT   (NGTOT*128)     // floats per timestep in packed layout
#define ETR    (NGTOT*4)       // 832 padded ET rows

typedef unsigned long long ull;

// ---------------- persistent device state (zero-initialized) ----------------
// Packed: W[t][ (i>>2)*128 + lane*4 + (i&3) ]  -> one LDG.128 per lane per 4 states.
// Groups >= 194 are never written -> stay 0 -> contribute 0 to sums.
__device__ float    g_W[NT][WFLT];       // 13.6 MB, L2-resident
__device__ float    g_dh[NT][NB];        // normalizer history (CTA0 writes)
__device__ float    g_scp[NCTA][NB];     // per-CTA score partials
__device__ unsigned g_count = 0;         // barrier arrivals
__device__ unsigned g_gen   = 0;         // barrier generation (monotone, replay-safe)

static __device__ __forceinline__ ull pk2(float x, float y) {
    ull r; asm("mov.b64 %0,{%1,%2};" : "=l"(r) : "f"(x), "f"(y)); return r;
}
static __device__ __forceinline__ void upk2(ull v, float& x, float& y) {
    asm("mov.b64 {%0,%1},%2;" : "=f"(x), "=f"(y) : "l"(v));
}
static __device__ __forceinline__ void ffma2(ull& a, ull b, ull c) {  // a += b*c (2x f32)
    asm("fma.rn.f32x2 %0,%1,%2,%0;" : "+l"(a) : "l"(b), "l"(c));
}
static __device__ __forceinline__ void fadd2(ull& a, ull b) {
    asm("add.rn.f32x2 %0,%1,%0;" : "+l"(a) : "l"(b));
}

// fence-light grid barrier: release-arrive, release-publish, acquire-spin
static __device__ __forceinline__ void gsync(unsigned& gen) {
    __syncthreads();
    if (threadIdx.x == 0) {
        gen += 1u;
        unsigned prev;
        asm volatile("atom.add.release.gpu.global.u32 %0,[%1],%2;"
                     : "=r"(prev) : "l"(&g_count), "r"(1u) : "memory");
        if (prev == NCTA - 1) {
            asm volatile("st.relaxed.gpu.global.u32 [%0],%1;" :: "l"(&g_count), "r"(0u) : "memory");
            asm volatile("st.release.gpu.global.u32 [%0],%1;" :: "l"(&g_gen), "r"(gen) : "memory");
        } else {
            unsigned v;
            do {
                asm volatile("ld.acquire.gpu.global.u32 %0,[%1];" : "=r"(v) : "l"(&g_gen) : "memory");
            } while (v != gen);
        }
    }
    __syncthreads();
}

#define PIDX(j) ((((j) >> 2) << 7) + (lane << 2) + ((j) & 3))

__global__ void __launch_bounds__(NTHR, 1)
crf_kernel(const float* __restrict__ em, const int* __restrict__ tags32,
           const float* __restrict__ mask, const float* __restrict__ trans,
           float* __restrict__ out)
{
    __shared__ __align__(16) float ET[ETR][8];       // exp(trans) col slice, [i][jc]
    __shared__ float s_part[NWARP][WJ][NB];
    __shared__ float s_d[NWARP][NB];

    const int tid  = threadIdx.x;
    const int w    = tid >> 5;
    const int lane = tid & 31;                       // lane == batch
    const int cta  = blockIdx.x;
    const int j0   = cta * WJ;

    unsigned gen = 0;
    if (tid == 0) gen = __ldcg(&g_gen);              // uniform at rest across CTAs

    // =============== INIT ===============
    for (int idx = tid; idx < ETR * 8; idx += NTHR) {
        int i = idx >> 3, jc = idx & 7, j = j0 + jc;
        float v = 0.f;
        if (i < S && j < S) v = __expf(trans[i * S + j]);   // exp(-1e9) -> 0
        (&ET[0][0])[idx] = v;
    }
    if (w < WJ) {                                    // W_0 slice
        int j = j0 + w;
        float v = 0.f;
        if (j < S) v = __expf(trans[j] + em[(size_t)lane * NT * S + j]);
        g_W[0][PIDX(j)] = v;
    }
    if (w == NWARP - 1) {                            // score gather (lane = batch)
        const bool is64 = (tags32[1] == 0);          // int64 high words zero (tags>=3)
        const int b = lane;
        float sc = 0.f;
        for (int t = cta + 1; t < NT; t += NCTA) {
            float m = mask[b * NT + t];
            int cur = is64 ? tags32[(b * NT + t) * 2]     : tags32[b * NT + t];
            int prv = is64 ? tags32[(b * NT + t - 1) * 2] : tags32[b * NT + t - 1];
            sc += (em[((size_t)b * NT + t) * S + cur] + trans[prv * S + cur]) * m;
        }
        if (cta == NCTA - 1) {                       // boundary terms
            int tag0 = is64 ? tags32[(b * NT) * 2] : tags32[b * NT];
            sc += trans[tag0] + em[(size_t)b * NT * S + tag0];
            float ms = 0.f;
            for (int t = 0; t < NT; t++) ms += mask[b * NT + t];
            int li = (int)ms - 1;
            int lt = is64 ? tags32[(b * NT + li) * 2] : tags32[b * NT + li];
            sc += trans[lt * S + 1];                 // last -> EOS
        }
        g_scp[cta][lane] = sc;
    }
    gsync(gen);

    const int gb = w * GW;                           // this warp's group base

    // =============== MAIN LOOP: 127 matvec steps ===============
    for (int t = 1; t < NT; ++t) {
        const float*  __restrict__ Wp = g_W[t - 1];
        float*        __restrict__ Wc = g_W[t];
        const float4* __restrict__ W4 = (const float4*)Wp;

        // depth-4 LDG.128 prolog (groups all in-range: gb+3 <= 198 < 208)
        float4 buf[4];
        #pragma unroll
        for (int k = 0; k < 4; k++) buf[k] = __ldcg(&W4[(gb + k) * 32 + lane]);

        // independent scalar prefetches (overlap W latency)
        float mk = 0.f, emv = 0.f, oldv = 0.f;
        const int j = j0 + w;
        if (w < WJ) {
            mk = mask[lane * NT + t];
            if (j < S) emv = em[((size_t)lane * NT + t) * S + j];
            oldv = __ldcg(&Wp[PIDX(j)]);             // own-CTA data from t-1
        }

        ull a0 = 0, a1 = 0, a2 = 0, a3 = 0, dp = 0;
        #pragma unroll
        for (int gg = 0; gg < GW; ++gg) {
            float4 u = buf[gg & 3];
            if (gg + 4 < GW) buf[gg & 3] = __ldcg(&W4[(gb + gg + 4) * 32 + lane]);
            const int i4 = (gb + gg) << 2;
            { ull uu = pk2(u.x, u.x);
              ulonglong2 ea = *(const ulonglong2*)&ET[i4 + 0][0];
              ulonglong2 eb = *(const ulonglong2*)&ET[i4 + 0][4];
              ffma2(a0, uu, ea.x); ffma2(a1, uu, ea.y); ffma2(a2, uu, eb.x); ffma2(a3, uu, eb.y); }
            { ull uu = pk2(u.y, u.y);
              ulonglong2 ea = *(const ulonglong2*)&ET[i4 + 1][0];
              ulonglong2 eb = *(const ulonglong2*)&ET[i4 + 1][4];
              ffma2(a0, uu, ea.x); ffma2(a1, uu, ea.y); ffma2(a2, uu, eb.x); ffma2(a3, uu, eb.y); }
            { ull uu = pk2(u.z, u.z);
              ulonglong2 ea = *(const ulonglong2*)&ET[i4 + 2][0];
              ulonglong2 eb = *(const ulonglong2*)&ET[i4 + 2][4];
              ffma2(a0, uu, ea.x); ffma2(a1, uu, ea.y); ffma2(a2, uu, eb.x); ffma2(a3, uu, eb.y); }
            { ull uu = pk2(u.w, u.w);
              ulonglong2 ea = *(const ulonglong2*)&ET[i4 + 3][0];
              ulonglong2 eb = *(const ulonglong2*)&ET[i4 + 3][4];
              ffma2(a0, uu, ea.x); ffma2(a1, uu, ea.y); ffma2(a2, uu, eb.x); ffma2(a3, uu, eb.y); }
            fadd2(dp, pk2(u.x, u.y));                // local normalizer (fixed order,
            fadd2(dp, pk2(u.z, u.w));                //  bitwise identical in every CTA)
        }

        float cs[8];
        upk2(a0, cs[0], cs[1]); upk2(a1, cs[2], cs[3]);
        upk2(a2, cs[4], cs[5]); upk2(a3, cs[6], cs[7]);
        float dx, dy; upk2(dp, dx, dy);
        #pragma unroll
        for (int k = 0; k < WJ; k++) s_part[w][k][lane] = cs[k];
        s_d[w][lane] = dx + dy;
        __syncthreads();

        if (w < WJ) {
            float ssum = 0.f, dsum = 0.f;
            #pragma unroll
            for (int ww = 0; ww < NWARP; ww++) {
                ssum += s_part[ww][w][lane];
                dsum += s_d[ww][lane];
            }
            float nv = (mk > 0.f)
                     ? (ssum * __fdividef(1.f, dsum) * __expf(emv))
                     : oldv;                         // masked step carries old value
            Wc[PIDX(j)] = nv;                        // j>=S stores 0 (ssum==0)
            if (cta == 0 && w == 0) g_dh[t - 1][lane] = dsum;
        }
        gsync(gen);                                  // orders Wc stores (release chain)
    }

    // =============== FINAL: log_z + score -> NLL (CTA 0) ===============
    if (cta == 0) {
        const int b = lane;
        float Lp = 0.f;
        for (int t = 1 + w; t < NT; t += NWARP)
            if (mask[b * NT + t] > 0.f) Lp += logf(g_dh[t - 1][b]);

        float zp = 0.f;
        const float* Wf = g_W[NT - 1];
        for (int jj = w; jj < S; jj += NWARP)
            zp += __ldcg(&Wf[PIDX(jj)]) * __expf(trans[jj * S + 1]);   // trans[j, EOS]

        s_part[w][0][lane] = Lp;
        s_part[w][1][lane] = zp;
        __syncthreads();
        if (w == 0) {
            float L = 0.f, zs = 0.f;
            #pragma unroll
            for (int ww = 0; ww < NWARP; ww++) {
                L  += s_part[ww][0][lane];
                zs += s_part[ww][1][lane];
            }
            float sc = 0.f;
            for (int c = 0; c < NCTA; c++) sc += g_scp[c][lane];
            float r = (L + logf(zs)) - sc;           // log_z - score per batch
            #pragma unroll
            for (int o = 16; o; o >>= 1) r += __shfl_xor_sync(0xffffffffu, r, o);
            if (lane == 0) out[0] = r;               // NLL
        }
    }
}

extern "C" void kernel_launch(void* const* d_in, const int* in_sizes, int n_in,
                              void* d_out, int out_size)
{
    (void)in_sizes; (void)n_in; (void)out_size;
    const float* em    = (const float*)d_in[0];
    const int*   tags  = (const int*)  d_in[1];   // int64 or int32, detected in-kernel
    const float* mask  = (const float*)d_in[2];
    const float* trans = (const float*)d_in[3];
    crf_kernel<<<NCTA, NTHR>>>(em, tags, mask, trans, (float*)d_out);
}

// round 5
// speedup vs baseline: 2.0861x; 1.1029x over previous
#include <cuda_runtime.h>

#define S      771             // STATE
#define NB     32              // batch == warp lanes
#define NT     128             // time
#define NCTA   148             // one CTA per SM, all co-resident
#define WJ     6               // output columns per CTA (148*6=888 >= 772)
#define NWARP  16
#define NTHR   512
#define GW     13              // i-groups (of 4 states) per warp
#define NIGRP  (NWARP*GW)      // 208 i-groups = 832 padded i-rows
#define NJGRP  222             // ceil(888/4) j-groups (write range)
#define WFLT   (NJGRP*128)     // floats per timestep in packed layout

typedef unsigned long long ull;

// ---------------- persistent device state ----------------
// Packed: W[t][ (i>>2)*128 + lane*4 + (i&3) ] -> one LDG.128 per lane per 4 states.
// Every group 0..221 is (re)written each run: zeros beyond j=771. Reads cover 0..207.
__device__ float    g_W[NT][WFLT];       // 14.6 MB, L2-resident
__device__ float    g_dh[NT][NB];        // normalizer history (CTA0 writes)
__device__ float    g_scp[NCTA][NB];     // per-CTA score partials
__device__ unsigned g_count = 0;         // barrier arrivals
__device__ unsigned g_gen   = 0;         // barrier generation (monotone, replay-safe)

static __device__ __forceinline__ ull pk2(float x, float y) {
    ull r; asm("mov.b64 %0,{%1,%2};" : "=l"(r) : "f"(x), "f"(y)); return r;
}
static __device__ __forceinline__ void upk2(ull v, float& x, float& y) {
    asm("mov.b64 {%0,%1},%2;" : "=f"(x), "=f"(y) : "l"(v));
}
static __device__ __forceinline__ void ffma2(ull& a, ull b, ull c) {  // a += b*c (2x f32)
    asm("fma.rn.f32x2 %0,%1,%2,%0;" : "+l"(a) : "l"(b), "l"(c));
}
static __device__ __forceinline__ void fadd2(ull& a, ull b) {
    asm("add.rn.f32x2 %0,%1,%0;" : "+l"(a) : "l"(b));
}

// fence-light grid barrier: release-arrive, release-publish, acquire-spin
static __device__ __forceinline__ void gsync(unsigned& gen) {
    __syncthreads();
    if (threadIdx.x == 0) {
        gen += 1u;
        unsigned prev;
        asm volatile("atom.add.release.gpu.global.u32 %0,[%1],%2;"
                     : "=r"(prev) : "l"(&g_count), "r"(1u) : "memory");
        if (prev == NCTA - 1) {
            asm volatile("st.relaxed.gpu.global.u32 [%0],%1;" :: "l"(&g_count), "r"(0u) : "memory");
            asm volatile("st.release.gpu.global.u32 [%0],%1;" :: "l"(&g_gen), "r"(gen) : "memory");
        } else {
            unsigned v;
            do {
                asm volatile("ld.acquire.gpu.global.u32 %0,[%1];" : "=r"(v) : "l"(&g_gen) : "memory");
            } while (v != gen);
        }
    }
    __syncthreads();
}

#define PIDX(j) ((((j) >> 2) << 7) + (lane << 2) + ((j) & 3))

__global__ void __launch_bounds__(NTHR, 1)
crf_kernel(const float* __restrict__ em, const int* __restrict__ tags32,
           const float* __restrict__ mask, const float* __restrict__ trans,
           float* __restrict__ out)
{
    __shared__ __align__(16) float ET[NIGRP*4][8];   // exp(trans), 32B row: 6 used + 2 pad
    __shared__ float s_part[NWARP][WJ][NB];
    __shared__ float s_d[NWARP][NB];

    const int tid  = threadIdx.x;
    const int w    = tid >> 5;
    const int lane = tid & 31;                       // lane == batch
    const int cta  = blockIdx.x;
    const int j0   = cta * WJ;

    unsigned gen = 0;
    if (tid == 0) gen = __ldcg(&g_gen);              // uniform at rest across CTAs

    // =============== INIT ===============
    for (int idx = tid; idx < NIGRP*4*8; idx += NTHR) {
        int i = idx >> 3, jc = idx & 7, j = j0 + jc;
        float v = 0.f;
        if (i < S && jc < WJ && j < S) v = __expf(trans[i * S + j]);  // exp(-1e9) -> 0
        (&ET[0][0])[idx] = v;
    }
    if (w < WJ) {                                    // W_0 slice (zeros for j>=S)
        int j = j0 + w;
        float v = 0.f;
        if (j < S) v = __expf(trans[j] + em[(size_t)lane * NT * S + j]);
        g_W[0][PIDX(j)] = v;
    }
    if (w == NWARP - 1) {                            // score gather (lane = batch)
        const bool is64 = (tags32[1] == 0);          // int64 high words zero (tags>=3)
        const int b = lane;
        float sc = 0.f;
        for (int t = cta + 1; t < NT; t += NCTA) {
            float m = mask[b * NT + t];
            int cur = is64 ? tags32[(b * NT + t) * 2]     : tags32[b * NT + t];
            int prv = is64 ? tags32[(b * NT + t - 1) * 2] : tags32[b * NT + t - 1];
            sc += (em[((size_t)b * NT + t) * S + cur] + trans[prv * S + cur]) * m;
        }
        if (cta == NCTA - 1) {                       // boundary terms
            int tag0 = is64 ? tags32[(b * NT) * 2] : tags32[b * NT];
            sc += trans[tag0] + em[(size_t)b * NT * S + tag0];
            float ms = 0.f;
            for (int t = 0; t < NT; t++) ms += mask[b * NT + t];
            int li = (int)ms - 1;
            int lt = is64 ? tags32[(b * NT + li) * 2] : tags32[b * NT + li];
            sc += trans[lt * S + 1];                 // last -> EOS
        }
        g_scp[cta][lane] = sc;
    }
    gsync(gen);

    const int gb = w * GW;                           // this warp's i-group base

    // =============== MAIN LOOP: 127 matvec steps ===============
    for (int t = 1; t < NT; ++t) {
        const float*  __restrict__ Wp = g_W[t - 1];
        float*        __restrict__ Wc = g_W[t];
        const float4* __restrict__ W4 = (const float4*)Wp;

        // depth-4 LDG.128 prolog (gb+3 <= 198 < 208, always in-range)
        float4 buf[4];
        #pragma unroll
        for (int k = 0; k < 4; k++) buf[k] = __ldcg(&W4[(gb + k) * 32 + lane]);

        // independent scalar prefetches (overlap W latency)
        float mk = 0.f, emv = 0.f, oldv = 0.f;
        const int j = j0 + w;
        if (w < WJ) {
            mk = mask[lane * NT + t];
            if (j < S) emv = em[((size_t)lane * NT + t) * S + j];
            oldv = __ldcg(&Wp[PIDX(j)]);             // own-CTA data from t-1
        }

        ull a0 = 0, a1 = 0, a2 = 0, dp = 0;          // col pairs (0,1)(2,3)(4,5) + d
        #pragma unroll
        for (int gg = 0; gg < GW; ++gg) {
            float4 u = buf[gg & 3];
            if (gg + 4 < GW) buf[gg & 3] = __ldcg(&W4[(gb + gg + 4) * 32 + lane]);
            const int i4 = (gb + gg) << 2;
            #pragma unroll
            for (int q = 0; q < 4; ++q) {
                float us = (q == 0) ? u.x : (q == 1) ? u.y : (q == 2) ? u.z : u.w;
                ull uu = pk2(us, us);
                ulonglong2 ea = *(const ulonglong2*)&ET[i4 + q][0];  // j01, j23
                ull        eb = *(const ull*)       &ET[i4 + q][4];  // j45
                ffma2(a0, uu, ea.x); ffma2(a1, uu, ea.y); ffma2(a2, uu, eb);
            }
            fadd2(dp, pk2(u.x, u.y));                // local normalizer (fixed order,
            fadd2(dp, pk2(u.z, u.w));                //  bitwise identical in every CTA)
        }

        float cs[WJ];
        upk2(a0, cs[0], cs[1]); upk2(a1, cs[2], cs[3]); upk2(a2, cs[4], cs[5]);
        float dx, dy; upk2(dp, dx, dy);
        #pragma unroll
        for (int k = 0; k < WJ; k++) s_part[w][k][lane] = cs[k];
        s_d[w][lane] = dx + dy;
        __syncthreads();

        if (w < WJ) {
            float ssum = 0.f, dsum = 0.f;
            #pragma unroll
            for (int ww = 0; ww < NWARP; ww++) {
                ssum += s_part[ww][w][lane];
                dsum += s_d[ww][lane];
            }
            float nv = (mk > 0.f)
                     ? (ssum * __fdividef(1.f, dsum) * __expf(emv))
                     : oldv;                         // masked step carries old value
            Wc[PIDX(j)] = nv;                        // j>=S stores 0 (ssum==0, emv==0)
            if (cta == 0 && w == 0) g_dh[t - 1][lane] = dsum;
        }
        gsync(gen);                                  // orders Wc stores (release chain)
    }

    // =============== FINAL: log_z + score -> NLL (CTA 0) ===============
    if (cta == 0) {
        const int b = lane;
        float Lp = 0.f;
        for (int t = 1 + w; t < NT; t += NWARP)
            if (mask[b * NT + t] > 0.f) Lp += logf(g_dh[t - 1][b]);

        float zp = 0.f;
        const float* Wf = g_W[NT - 1];
        for (int jj = w; jj < S; jj += NWARP)
            zp += __ldcg(&Wf[PIDX(jj)]) * __expf(trans[jj * S + 1]);   // trans[j, EOS]

        s_part[w][0][lane] = Lp;
        s_part[w][1][lane] = zp;
        __syncthreads();
        if (w == 0) {
            float L = 0.f, zs = 0.f;
            #pragma unroll
            for (int ww = 0; ww < NWARP; ww++) {
                L  += s_part[ww][0][lane];
                zs += s_part[ww][1][lane];
            }
            float sc = 0.f;
            for (int c = 0; c < NCTA; c++) sc += g_scp[c][lane];
            float r = (L + logf(zs)) - sc;           // log_z - score per batch
            #pragma unroll
            for (int o = 16; o; o >>= 1) r += __shfl_xor_sync(0xffffffffu, r, o);
            if (lane == 0) out[0] = r;               // NLL
        }
    }
}

extern "C" void kernel_launch(void* const* d_in, const int* in_sizes, int n_in,
                              void* d_out, int out_size)
{
    (void)in_sizes; (void)n_in; (void)out_size;
    const float* em    = (const float*)d_in[0];
    const int*   tags  = (const int*)  d_in[1];   // int64 or int32, detected in-kernel
    const float* mask  = (const float*)d_in[2];
    const float* trans = (const float*)d_in[3];
    crf_kernel<<<NCTA, NTHR>>>(em, tags, mask, trans, (float*)d_out);
}

// round 7
// speedup vs baseline: 2.1048x; 1.0090x over previous
#include <cuda_runtime.h>
#include <cuda_bf16.h>
#include <cstdint>

#define S        771                 // STATE
#define JP       832                 // padded states = 52*16
#define NB       32                  // batch
#define NT       128                 // time
#define NCTA     52                  // 52*16 = 832 output columns
#define WJ       16                  // j columns per CTA
#define NWARP    8
#define NTHR     256
#define KT       13                  // k-tiles (of 16) per k-quarter
#define INV1024  (1.0f/1024.0f)
#define LSUM     880.2969192511308f  // 127 * ln(1024)

// ---------------- persistent device state ----------------
__device__ __align__(16) __nv_bfloat16 g_Wbf[2][NB][JP];    // scaled alphas, bf16
__device__ __align__(16) float g_EME[(size_t)NT * JP * NB]; // exp(em)/1024, [t][j][b]
__device__ float    g_scp[NCTA][NB];   // per-CTA score partials
__device__ unsigned g_count = 0;       // barrier arrivals
__device__ unsigned g_gen   = 0;       // barrier generation (monotone, replay-safe)

// fence-light grid barrier (proven R3-R5)
static __device__ __forceinline__ void gsync(unsigned& gen) {
    __syncthreads();
    if (threadIdx.x == 0) {
        gen += 1u;
        unsigned prev;
        asm volatile("atom.add.release.gpu.global.u32 %0,[%1],%2;"
                     : "=r"(prev) : "l"(&g_count), "r"(1u) : "memory");
        if (prev == NCTA - 1) {
            asm volatile("st.relaxed.gpu.global.u32 [%0],%1;" :: "l"(&g_count), "r"(0u) : "memory");
            asm volatile("st.release.gpu.global.u32 [%0],%1;" :: "l"(&g_gen), "r"(gen) : "memory");
        } else {
            unsigned v;
            do {
                asm volatile("ld.acquire.gpu.global.u32 %0,[%1];" : "=r"(v) : "l"(&g_gen) : "memory");
            } while (v != gen);
        }
    }
    __syncthreads();
}

static __device__ __forceinline__ uint32_t pack_bf16x2(float lo, float hi) {
    uint32_t r;
    asm("cvt.rn.bf16x2.f32 %0,%1,%2;" : "=r"(r) : "f"(hi), "f"(lo));
    return r;
}
static __device__ __forceinline__ void mma16816(float* c, uint32_t a0, uint32_t a1,
                                                uint32_t a2, uint32_t a3,
                                                uint32_t b0, uint32_t b1) {
    asm volatile("mma.sync.aligned.m16n8k16.row.col.f32.bf16.bf16.f32 "
                 "{%0,%1,%2,%3},{%4,%5,%6,%7},{%8,%9},{%0,%1,%2,%3};"
                 : "+f"(c[0]), "+f"(c[1]), "+f"(c[2]), "+f"(c[3])
                 : "r"(a0), "r"(a1), "r"(a2), "r"(a3), "r"(b0), "r"(b1));
}

__global__ void __launch_bounds__(NTHR, 1)
crf_kernel(const float* __restrict__ em, const int* __restrict__ tags32,
           const float* __restrict__ mask, const float* __restrict__ trans,
           float* __restrict__ out)
{
    __shared__ __align__(16) float s_D[4][32][18];   // k-quarter partials, padded
    __shared__ float s_fin[NWARP][NB];

    const int tid  = threadIdx.x;
    const int w    = tid >> 5;
    const int lane = tid & 31;
    const int g    = lane >> 2;        // MMA group id
    const int tg   = lane & 3;         // MMA thread-in-group
    const int cta  = blockIdx.x;
    const int j0   = cta * WJ;
    const int mt   = w >> 2;           // m-tile (batch half)
    const int kq   = w & 3;            // k-quarter
    const int kb0  = kq * (KT * 16);   // k base = kq*208

    // epilogue role: thread -> (batch b_e, j-pair jp_e)
    const int b_e  = tid >> 3;
    const int jp_e = tid & 7;
    const int jl_e = jp_e * 2;

    unsigned gen = 0;
    if (tid == 0) gen = __ldcg(&g_gen);

    // =============== INIT ===============
    // B fragments (E^T slice) -> constant registers. B[k][n]: rows i, col j.
    uint32_t bf[KT][2][2];
    #pragma unroll
    for (int kt = 0; kt < KT; kt++) {
        #pragma unroll
        for (int nt = 0; nt < 2; nt++) {
            const int jg = j0 + nt * 8 + g;
            #pragma unroll
            for (int r = 0; r < 2; r++) {
                const int i0 = kb0 + kt * 16 + 2 * tg + 8 * r;
                float lo = (i0     < S && jg < S) ? __expf(trans[(i0    ) * S + jg]) : 0.f;
                float hi = (i0 + 1 < S && jg < S) ? __expf(trans[(i0 + 1) * S + jg]) : 0.f;
                bf[kt][nt][r] = pack_bf16x2(lo, hi);
            }
        }
    }
    // W_0 slice: W0[b][j] = exp(trans[BOS=0][j] + em[b,0,j]); padded j -> 0
    {
        const int ja = j0 + jl_e, jb = ja + 1;
        float f0 = (ja < S) ? __expf(trans[ja] + em[(size_t)b_e * NT * S + ja]) : 0.f;
        float f1 = (jb < S) ? __expf(trans[jb] + em[(size_t)b_e * NT * S + jb]) : 0.f;
        reinterpret_cast<uint32_t*>(&g_Wbf[0][b_e][j0])[jp_e] = pack_bf16x2(f0, f1);
    }
    // EME[t][j][b] = exp(em[b,t,j]) / 1024  (zero for padded j); t=0 row unused
    for (size_t id = (size_t)JP + (size_t)cta * NTHR + tid; id < (size_t)NT * JP;
         id += (size_t)NCTA * NTHR) {
        int t = (int)(id / JP), j = (int)(id % JP);
        float4* dst = reinterpret_cast<float4*>(&g_EME[id * NB]);
        if (j < S) {
            #pragma unroll
            for (int b0 = 0; b0 < NB; b0 += 4) {
                float4 v;
                v.x = __expf(em[((size_t)(b0 + 0) * NT + t) * S + j]) * INV1024;
                v.y = __expf(em[((size_t)(b0 + 1) * NT + t) * S + j]) * INV1024;
                v.z = __expf(em[((size_t)(b0 + 2) * NT + t) * S + j]) * INV1024;
                v.w = __expf(em[((size_t)(b0 + 3) * NT + t) * S + j]) * INV1024;
                dst[b0 >> 2] = v;
            }
        } else {
            float4 z = {0.f, 0.f, 0.f, 0.f};
            #pragma unroll
            for (int b0 = 0; b0 < NB; b0 += 4) dst[b0 >> 2] = z;
        }
    }
    // score gather (warp 7; lane = batch)
    if (w == NWARP - 1) {
        const bool is64 = (tags32[1] == 0);   // int64 high words zero (tags>=3)
        const int b = lane;
        float sc = 0.f;
        for (int t = cta + 1; t < NT; t += NCTA) {
            float m = mask[b * NT + t];
            int cur = is64 ? tags32[(b * NT + t) * 2]     : tags32[b * NT + t];
            int prv = is64 ? tags32[(b * NT + t - 1) * 2] : tags32[b * NT + t - 1];
            sc += (em[((size_t)b * NT + t) * S + cur] + trans[prv * S + cur]) * m;
        }
        if (cta == NCTA - 1) {
            int tag0 = is64 ? tags32[(b * NT) * 2] : tags32[b * NT];
            sc += trans[tag0] + em[(size_t)b * NT * S + tag0];
            float ms = 0.f;
            for (int t = 0; t < NT; t++) ms += mask[b * NT + t];
            int li = (int)ms - 1;
            int lt = is64 ? tags32[(b * NT + li) * 2] : tags32[b * NT + li];
            sc += trans[lt * S + 1];          // last -> EOS
        }
        g_scp[cta][lane] = sc;
    }
    gsync(gen);

    const int rowA = mt * 16 + g;             // A rows this thread touches
    const int kwof = (kb0 >> 1) + tg;         // u32 col index base within a W row

    // =============== MAIN LOOP: 127 GEMM steps ===============
    for (int t = 1; t < NT; ++t) {
        const int prev = (t - 1) & 1, cur = t & 1;

        // epilogue prefetch (independent of this step's producers? no - EME/mask only)
        const float mk = mask[b_e * NT + t];
        const float e0 = g_EME[((size_t)t * JP + j0 + jl_e) * NB + b_e];
        const float e1 = g_EME[((size_t)t * JP + j0 + jl_e + 1) * NB + b_e];

        // ---- MMA: A = W[prev] streamed, B = E const regs ----
        const uint32_t* pr0 = reinterpret_cast<const uint32_t*>(g_Wbf[prev])
                            + (size_t)rowA * (JP / 2);
        const uint32_t* pr1 = pr0 + 8 * (JP / 2);
        float c0[4] = {0.f, 0.f, 0.f, 0.f};
        float c1[4] = {0.f, 0.f, 0.f, 0.f};
        #pragma unroll
        for (int kt = 0; kt < KT; kt++) {
            const int kw = kwof + kt * 8;
            uint32_t a0 = __ldcg(pr0 + kw);
            uint32_t a2 = __ldcg(pr0 + kw + 4);
            uint32_t a1 = __ldcg(pr1 + kw);
            uint32_t a3 = __ldcg(pr1 + kw + 4);
            mma16816(c0, a0, a1, a2, a3, bf[kt][0][0], bf[kt][0][1]);
            mma16816(c1, a0, a1, a2, a3, bf[kt][1][0], bf[kt][1][1]);
        }
        // partial store: D[m=b][n=j-local]
        {
            float2* p00 = reinterpret_cast<float2*>(&s_D[kq][rowA    ][0 * 8 + 2 * tg]);
            float2* p01 = reinterpret_cast<float2*>(&s_D[kq][rowA + 8][0 * 8 + 2 * tg]);
            float2* p10 = reinterpret_cast<float2*>(&s_D[kq][rowA    ][1 * 8 + 2 * tg]);
            float2* p11 = reinterpret_cast<float2*>(&s_D[kq][rowA + 8][1 * 8 + 2 * tg]);
            *p00 = make_float2(c0[0], c0[1]);
            *p01 = make_float2(c0[2], c0[3]);
            *p10 = make_float2(c1[0], c1[1]);
            *p11 = make_float2(c1[2], c1[3]);
        }
        __syncthreads();

        // ---- epilogue: reduce k-quarters, scale by exp(em)/1024, pack bf16 ----
        float s0 = 0.f, s1 = 0.f;
        #pragma unroll
        for (int q = 0; q < 4; q++) {
            s0 += s_D[q][b_e][jl_e];
            s1 += s_D[q][b_e][jl_e + 1];
        }
        float nv0 = s0 * e0, nv1 = s1 * e1;
        if (mk <= 0.f) {                       // masked step: carry old (exact 2^-10)
            uint32_t old = reinterpret_cast<const uint32_t*>(&g_Wbf[prev][b_e][j0])[jp_e];
            nv0 = __uint_as_float(old << 16)         * INV1024;
            nv1 = __uint_as_float(old & 0xFFFF0000u) * INV1024;
        }
        reinterpret_cast<uint32_t*>(&g_Wbf[cur][b_e][j0])[jp_e] = pack_bf16x2(nv0, nv1);

        gsync(gen);                            // publishes W_t (release chain)
    }

    // =============== FINAL: log_z + score -> NLL (CTA 0) ===============
    if (cta == 0) {
        const int b = lane;
        float zp = 0.f;
        for (int j = w; j < S; j += NWARP)
            zp += __bfloat162float(g_Wbf[1][b][j]) * __expf(trans[j * S + 1]);
        s_fin[w][lane] = zp;
        __syncthreads();
        if (w == 0) {
            float zs = 0.f;
            #pragma unroll
            for (int ww = 0; ww < NWARP; ww++) zs += s_fin[ww][lane];
            float sc = 0.f;
            for (int c = 0; c < NCTA; c++) sc += g_scp[c][lane];
            float r = (logf(zs) + LSUM) - sc;  // log_z - score per batch
            #pragma unroll
            for (int o = 16; o; o >>= 1) r += __shfl_xor_sync(0xffffffffu, r, o);
            if (lane == 0) out[0] = r;         // NLL
        }
    }
}

extern "C" void kernel_launch(void* const* d_in, const int* in_sizes, int n_in,
                              void* d_out, int out_size)
{
    (void)in_sizes; (void)n_in; (void)out_size;
    const float* em    = (const float*)d_in[0];
    const int*   tags  = (const int*)  d_in[1];   // int64 or int32, detected in-kernel
    const float* mask  = (const float*)d_in[2];
    const float* trans = (const float*)d_in[3];
    crf_kernel<<<NCTA, NTHR>>>(em, tags, mask, trans, (float*)d_out);
}